// round 6
// baseline (speedup 1.0000x reference)
#include <cuda_runtime.h>
#include <math.h>
#include <stdint.h>

// ---------------------------------------------------------------- constants
#define B_   64
#define S_   1000
#define D_   512          // N of the GEMM
#define K2_  1024         // K of the GEMM
#define M_   (B_ * S_)    // 64000

#define TMM  128          // CTA M tile
#define KCI  128          // K per chunk (128 int8 = 128B swizzled rows)
#define NCHI 8            // K2_/KCI
#define NPASS 4           // N passes of 128 cols each

// ------------------------------------------------------------- device scratch
__device__ float g_hW[B_ * D_];
__device__ float g_logits[M_];
__device__ int   g_maxA = 0;           // float bits of max|enc|
__device__ int   g_maxW = 0;           // float bits of max|W_bot|
// enc 2-level int8: plain row-major [M_][K2_]
__device__ __align__(16) uint8_t g_enc_h[(size_t)M_ * K2_];
__device__ __align__(16) uint8_t g_enc_l[(size_t)M_ * K2_];
// W_bot 2-level int8, transposed [chunk 8][n 512][k 128] (plain, swizzle at cp.async)
__device__ __align__(16) uint8_t g_w_h[NCHI * D_ * KCI];
__device__ __align__(16) uint8_t g_w_l[NCHI * D_ * KCI];

// ---------------------------------------------------------------- smem layout
// A: [stage][h/l][128 rows][128B] -> 64KB ; B: same -> 64KB
#define SA_I(st, pl)  ((st) * 32768 + (pl) * 16384)
#define SB_I(st, pl)  (65536 + (st) * 32768 + (pl) * 16384)
#define SM_SV   131072
#define SM_HW0  133120
#define SM_HW1  135168
#define SM_RS   137216
#define SM_TOTAL 137984

// ---------------------------------------------------------------- helpers
__device__ __forceinline__ uint32_t smem_u32(const void* p) {
    uint32_t a;
    asm("{ .reg .u64 t; cvta.to.shared.u64 t, %1; cvt.u32.u64 %0, t; }" : "=r"(a) : "l"(p));
    return a;
}
#define LDSM4(R, A)                                                             \
    asm volatile("ldmatrix.sync.aligned.m8n8.x4.shared.b16 {%0,%1,%2,%3}, [%4];" \
        : "=r"((R)[0]), "=r"((R)[1]), "=r"((R)[2]), "=r"((R)[3]) : "r"(A))
__device__ __forceinline__ void mma_s8(int* c, const uint32_t* a, const uint32_t* b) {
    asm volatile("mma.sync.aligned.m16n8k32.row.col.s32.s8.s8.s32 "
        "{%0,%1,%2,%3},{%4,%5,%6,%7},{%8,%9},{%0,%1,%2,%3};"
        : "+r"(c[0]), "+r"(c[1]), "+r"(c[2]), "+r"(c[3])
        : "r"(a[0]), "r"(a[1]), "r"(a[2]), "r"(a[3]), "r"(b[0]), "r"(b[1]));
}
#define CP16(dst, src) \
    asm volatile("cp.async.cg.shared.global [%0], [%1], 16;" :: "r"(dst), "l"(src) : "memory")
#define CP_COMMIT() asm volatile("cp.async.commit_group;" ::: "memory")
#define CP_WAIT0()  asm volatile("cp.async.wait_group 0;" ::: "memory")
#define CP_WAIT1()  asm volatile("cp.async.wait_group 1;" ::: "memory")

// x ~= alpha*(h + l/256), alpha = max/127, inv = 127/max
__device__ __forceinline__ void quant2(float x, float inv, int& h, int& l) {
    float q = x * inv;
    float hf = rintf(q);
    float lf = rintf((q - hf) * 256.f);
    lf = fminf(fmaxf(lf, -127.f), 127.f);
    h = (int)hf;
    l = (int)lf;
}

// ---------------------------------------------------------------------------
// max|.| reduction over enc (blocks 0..2047) and W_bot (blocks 2048..2063)
// ---------------------------------------------------------------------------
__global__ __launch_bounds__(256)
void max_kernel(const float* __restrict__ enc, const float* __restrict__ attn_w) {
    __shared__ float red[8];
    const int b = blockIdx.x;
    const int t = threadIdx.x;
    float m = 0.f;
    if (b < 2048) {
        const size_t base = (size_t)b * 32768;
        const size_t lim = (size_t)M_ * K2_;
        for (int j = 0; j < 128; j++) {
            size_t idx = base + (size_t)j * 256 + t;
            if (idx < lim) m = fmaxf(m, fabsf(enc[idx]));
        }
    } else {
        const size_t base = (size_t)D_ * D_ + (size_t)(b - 2048) * 32768;
        for (int j = 0; j < 128; j++)
            m = fmaxf(m, fabsf(attn_w[base + (size_t)j * 256 + t]));
    }
    #pragma unroll
    for (int o = 16; o > 0; o >>= 1) m = fmaxf(m, __shfl_xor_sync(0xffffffffu, m, o));
    if ((t & 31) == 0) red[t >> 5] = m;
    __syncthreads();
    if (t == 0) {
        #pragma unroll
        for (int i = 1; i < 8; i++) m = fmaxf(m, red[i]);
        atomicMax(b < 2048 ? &g_maxA : &g_maxW, __float_as_int(m));
    }
}

// ---------------------------------------------------------------------------
// enc -> 2-level int8, row-major.  grid(16000), block(256): 4 rows/CTA
// ---------------------------------------------------------------------------
__global__ __launch_bounds__(256)
void quant_enc_kernel(const float* __restrict__ enc) {
    const float inv = 127.f / __int_as_float(g_maxA);
    const int row = blockIdx.x * 4 + (threadIdx.x >> 6);
    const int c0  = (threadIdx.x & 63) * 16;
    const float4* p = reinterpret_cast<const float4*>(enc + (size_t)row * K2_ + c0);
    uint32_t hw_[4], lw_[4];
    #pragma unroll
    for (int q = 0; q < 4; q++) {
        float4 f = p[q];
        int h0, l0, h1, l1, h2, l2, h3, l3;
        quant2(f.x, inv, h0, l0);
        quant2(f.y, inv, h1, l1);
        quant2(f.z, inv, h2, l2);
        quant2(f.w, inv, h3, l3);
        hw_[q] = (h0 & 255) | ((h1 & 255) << 8) | ((h2 & 255) << 16) | ((uint32_t)(h3 & 255) << 24);
        lw_[q] = (l0 & 255) | ((l1 & 255) << 8) | ((l2 & 255) << 16) | ((uint32_t)(l3 & 255) << 24);
    }
    *reinterpret_cast<uint4*>(g_enc_h + (size_t)row * K2_ + c0) =
        make_uint4(hw_[0], hw_[1], hw_[2], hw_[3]);
    *reinterpret_cast<uint4*>(g_enc_l + (size_t)row * K2_ + c0) =
        make_uint4(lw_[0], lw_[1], lw_[2], lw_[3]);
}

// ---------------------------------------------------------------------------
// W_bot -> 2-level int8, transposed [chunk][n][k].  grid(8), block(512)
// ---------------------------------------------------------------------------
__global__ __launch_bounds__(512)
void quant_w_kernel(const float* __restrict__ attn_w) {
    const float inv = 127.f / __int_as_float(g_maxW);
    const int chunk = blockIdx.x;
    const int n = threadIdx.x;
    uint8_t* dh = g_w_h + (size_t)chunk * (D_ * KCI) + (size_t)n * KCI;
    uint8_t* dl = g_w_l + (size_t)chunk * (D_ * KCI) + (size_t)n * KCI;
    for (int k4 = 0; k4 < KCI; k4 += 4) {
        uint32_t hw_ = 0, lw_ = 0;
        #pragma unroll
        for (int j = 0; j < 4; j++) {
            const int kg = D_ + chunk * KCI + k4 + j;
            float w = attn_w[(size_t)kg * D_ + n];    // coalesced over n
            int h, l;
            quant2(w, inv, h, l);
            hw_ |= (uint32_t)(h & 255) << (j * 8);
            lw_ |= (uint32_t)(l & 255) << (j * 8);
        }
        *reinterpret_cast<uint32_t*>(dh + k4) = hw_;
        *reinterpret_cast<uint32_t*>(dl + k4) = lw_;
    }
}

// ---------------------------------------------------------------------------
// hW[b][n] = attn_b[n] + hidden[b] @ W_top[:,n]  (exact fp32)  grid(64,4) x 128
// ---------------------------------------------------------------------------
__global__ void hw_kernel(const float* __restrict__ hidden,
                          const float* __restrict__ attn_w,
                          const float* __restrict__ attn_b) {
    __shared__ float sh[D_];
    const int b = blockIdx.x;
    const int n = blockIdx.y * 128 + threadIdx.x;
    for (int i = threadIdx.x; i < D_; i += 128) sh[i] = hidden[b * D_ + i];
    __syncthreads();
    float a0 = 0.f, a1 = 0.f, a2 = 0.f, a3 = 0.f;
    #pragma unroll 4
    for (int k = 0; k < D_; k += 4) {
        a0 += sh[k + 0] * attn_w[(k + 0) * D_ + n];
        a1 += sh[k + 1] * attn_w[(k + 1) * D_ + n];
        a2 += sh[k + 2] * attn_w[(k + 2) * D_ + n];
        a3 += sh[k + 3] * attn_w[(k + 3) * D_ + n];
    }
    g_hW[b * D_ + n] = attn_b[n] + ((a0 + a1) + (a2 + a3));
}

// ---------------------------------------------------------------------------
// Main IMMA GEMM + tanh + v-dot. grid(500), block(512) = 16 warps (4M x 4N)
// 3-term 2-level int8: hh + (h*l + l*h)/256, fp32 finish.
// ---------------------------------------------------------------------------
__global__ __launch_bounds__(512, 1)
void gemm_kernel(const float* __restrict__ v) {
    extern __shared__ __align__(1024) uint8_t smem[];
    const uint32_t sb = smem_u32(smem);
    const int tid  = threadIdx.x;
    const int wid  = tid >> 5;
    const int lane = tid & 31;
    const int wm   = wid >> 2;          // 0..3 (32 M rows)
    const int wn   = wid & 3;           // 0..3 (32 N cols per pass)
    const int m0   = blockIdx.x * TMM;

    const float sAB = (__int_as_float(g_maxA) * (1.f / 127.f)) *
                      (__int_as_float(g_maxW) * (1.f / 127.f));

    float* svp = reinterpret_cast<float*>(smem + SM_SV);
    float* hw0 = reinterpret_cast<float*>(smem + SM_HW0);
    float* hw1 = reinterpret_cast<float*>(smem + SM_HW1);
    float* rsm = reinterpret_cast<float*>(smem + SM_RS);

    const int b0 = m0 / S_;
    const int b1 = (m0 + TMM - 1) / S_;
    const int thr = (b0 + 1) * S_ - m0;   // rows >= thr belong to b1
    for (int i = tid; i < D_; i += 512) {
        svp[i] = v[i];
        hw0[i] = g_hW[b0 * D_ + i];
        hw1[i] = g_hW[b1 * D_ + i];
    }
    if (tid < TMM) rsm[tid] = 0.f;
    __syncthreads();

    // ---- per-lane ldmatrix address components ------------------------------
    // A (m16 x k32 int8): lanes 0-15 rows, lanes>=16 k+16 bytes
    const int a_r16 = lane & 15;
    const uint32_t a_kext = (lane >> 4) << 4;
    uint32_t aoff[2], asw[2];
    #pragma unroll
    for (int ms = 0; ms < 2; ms++) {
        int r = wm * 32 + ms * 16 + a_r16;
        aoff[ms] = (uint32_t)r * 128;
        asw[ms]  = (uint32_t)(r & 7) << 4;
    }
    // B (n16 x k32 int8): lanes {0-7,16-23} n rows, lanes with bit3 k+16
    const int b_r16 = (lane & 7) | ((lane & 16) >> 1);
    const uint32_t b_kext = (lane & 8) << 1;
    uint32_t boff[2], bsw[2];
    #pragma unroll
    for (int f2 = 0; f2 < 2; f2++) {
        int r = wn * 32 + f2 * 16 + b_r16;
        boff[f2] = (uint32_t)r * 128;
        bsw[f2]  = (uint32_t)(r & 7) << 4;
    }

    // ---- cp.async loader (A: 128x128B x2 planes; B: 128x128B x2 planes) -----
    auto loadAB = [&](int pass, int chunk, int st) {
        #pragma unroll
        for (int pl = 0; pl < 2; pl++) {
            const uint8_t* gA = pl ? g_enc_l : g_enc_h;
            #pragma unroll
            for (int j = 0; j < 2; j++) {
                uint32_t p = (uint32_t)tid + j * 512;
                uint32_t row = p >> 3, c16 = p & 7;
                uint32_t dsto = row * 128 + ((c16 << 4) ^ ((row & 7) << 4));
                size_t   srco = (size_t)(m0 + row) * K2_ + chunk * KCI + (c16 << 4);
                CP16(sb + SA_I(st, pl) + dsto, gA + srco);
            }
        }
        #pragma unroll
        for (int pl = 0; pl < 2; pl++) {
            const uint8_t* gB = pl ? g_w_l : g_w_h;
            #pragma unroll
            for (int j = 0; j < 2; j++) {
                uint32_t p = (uint32_t)tid + j * 512;
                uint32_t row = p >> 3, c16 = p & 7;
                uint32_t dsto = row * 128 + ((c16 << 4) ^ ((row & 7) << 4));
                size_t   srco = (size_t)chunk * (D_ * KCI) +
                                (size_t)(pass * 128 + row) * KCI + (c16 << 4);
                CP16(sb + SB_I(st, pl) + dsto, gB + srco);
            }
        }
        CP_COMMIT();
    };

    int hh[2][4][4], cx[2][4][4];

    auto compute = [&](int st) {
        const uint32_t bAh = sb + SA_I(st, 0);
        const uint32_t bAl = sb + SA_I(st, 1);
        const uint32_t bBh = sb + SB_I(st, 0);
        const uint32_t bBl = sb + SB_I(st, 1);
        #pragma unroll
        for (int kk = 0; kk < 4; kk++) {
            const uint32_t ka = (uint32_t)(kk * 32) + a_kext;
            const uint32_t kb = (uint32_t)(kk * 32) + b_kext;
            uint32_t ah[2][4], al[2][4];
            #pragma unroll
            for (int ms = 0; ms < 2; ms++) {
                uint32_t o = aoff[ms] + (ka ^ asw[ms]);
                LDSM4(ah[ms], bAh + o);
                LDSM4(al[ms], bAl + o);
            }
            #pragma unroll
            for (int f2 = 0; f2 < 2; f2++) {
                const uint32_t o = boff[f2] + (kb ^ bsw[f2]);
                uint32_t bhf[4], blf[4];
                LDSM4(bhf, bBh + o);
                LDSM4(blf, bBl + o);
                #pragma unroll
                for (int ms = 0; ms < 2; ms++) {
                    mma_s8(hh[ms][f2 * 2 + 0], ah[ms], bhf + 0);
                    mma_s8(hh[ms][f2 * 2 + 1], ah[ms], bhf + 2);
                    mma_s8(cx[ms][f2 * 2 + 0], ah[ms], blf + 0);
                    mma_s8(cx[ms][f2 * 2 + 1], ah[ms], blf + 2);
                    mma_s8(cx[ms][f2 * 2 + 0], al[ms], bhf + 0);
                    mma_s8(cx[ms][f2 * 2 + 1], al[ms], bhf + 2);
                }
            }
        }
    };

    const int gid = lane >> 2;
    const int tig = lane & 3;

    // ======================= four N-passes (128 cols each) ==================
    #pragma unroll 1
    for (int pass = 0; pass < NPASS; pass++) {
        #pragma unroll
        for (int ms = 0; ms < 2; ms++)
            #pragma unroll
            for (int f = 0; f < 4; f++)
                #pragma unroll
                for (int c = 0; c < 4; c++) { hh[ms][f][c] = 0; cx[ms][f][c] = 0; }

        loadAB(pass, 0, 0);

        #pragma unroll 1
        for (int i = 0; i < NCHI; i++) {
            const int s = i & 1;
            const bool pf = (i + 1 < NCHI);
            if (pf) { loadAB(pass, i + 1, s ^ 1); CP_WAIT1(); }
            else    { CP_WAIT0(); }
            __syncthreads();
            compute(s);
            __syncthreads();
        }

        // epilogue: x = sAB*(hh + cx/256) + hW; rowsum += v * tanh(x)
        #pragma unroll
        for (int ms = 0; ms < 2; ms++) {
            #pragma unroll
            for (int ch = 0; ch < 2; ch++) {
                const int row = wm * 32 + ms * 16 + ch * 8 + gid;
                const float* hwrow = (row >= thr) ? hw1 : hw0;
                float rs = 0.f;
                #pragma unroll
                for (int f = 0; f < 4; f++) {
                    const int n = pass * 128 + wn * 32 + f * 8 + tig * 2;
                    float x0 = fmaf((float)cx[ms][f][ch * 2 + 0], 1.f / 256.f,
                                    (float)hh[ms][f][ch * 2 + 0]) * sAB + hwrow[n];
                    float x1 = fmaf((float)cx[ms][f][ch * 2 + 1], 1.f / 256.f,
                                    (float)hh[ms][f][ch * 2 + 1]) * sAB + hwrow[n + 1];
                    rs += svp[n] * tanhf(x0) + svp[n + 1] * tanhf(x1);
                }
                rs += __shfl_xor_sync(0xffffffffu, rs, 1);
                rs += __shfl_xor_sync(0xffffffffu, rs, 2);
                if (tig == 0) atomicAdd(&rsm[row], rs);
            }
        }
    }

    __syncthreads();
    if (tid < TMM) g_logits[m0 + tid] = rsm[tid];
}

// ---------------------------------------------------------------------------
// softmax over S per batch. grid(64), block(256)
// ---------------------------------------------------------------------------
__global__ void softmax_kernel(float* __restrict__ out) {
    __shared__ float red[256];
    const int b = blockIdx.x;
    const int t = threadIdx.x;
    const float* row = g_logits + b * S_;
    float* orow = out + b * S_;

    float mx = -INFINITY;
    for (int i = t; i < S_; i += 256) mx = fmaxf(mx, row[i]);
    red[t] = mx;
    __syncthreads();
    for (int off = 128; off > 0; off >>= 1) {
        if (t < off) red[t] = fmaxf(red[t], red[t + off]);
        __syncthreads();
    }
    mx = red[0];
    __syncthreads();

    float sum = 0.f;
    for (int i = t; i < S_; i += 256) {
        float e = expf(row[i] - mx);
        orow[i] = e;
        sum += e;
    }
    red[t] = sum;
    __syncthreads();
    for (int off = 128; off > 0; off >>= 1) {
        if (t < off) red[t] += red[t + off];
        __syncthreads();
    }
    const float inv = 1.f / red[0];
    __syncthreads();
    for (int i = t; i < S_; i += 256) orow[i] *= inv;
}

// ---------------------------------------------------------------------------
extern "C" void kernel_launch(void* const* d_in, const int* in_sizes, int n_in,
                              void* d_out, int out_size) {
    const float* hidden = (const float*)d_in[0];   // [64, 512]
    const float* enc    = (const float*)d_in[1];   // [64, 1000, 1024]
    const float* attn_w = (const float*)d_in[2];   // [1536, 512]
    const float* attn_b = (const float*)d_in[3];   // [512]
    const float* v      = (const float*)d_in[4];   // [512]
    float* out = (float*)d_out;                    // [64, 1000]

    cudaFuncSetAttribute(gemm_kernel,
                         cudaFuncAttributeMaxDynamicSharedMemorySize, SM_TOTAL);

    max_kernel<<<2064, 256>>>(enc, attn_w);
    quant_enc_kernel<<<M_ / 4, 256>>>(enc);
    quant_w_kernel<<<NCHI, 512>>>(attn_w);
    hw_kernel<<<dim3(B_, 4), 128>>>(hidden, attn_w, attn_b);
    gemm_kernel<<<M_ / TMM, 512, SM_TOTAL>>>(v);
    softmax_kernel<<<B_, 256>>>(out);
}

// round 7
// speedup vs baseline: 3.0301x; 3.0301x over previous
#include <cuda_runtime.h>
#include <cuda_bf16.h>
#include <math.h>
#include <stdint.h>

// ---------------------------------------------------------------- constants
#define B_   64
#define S_   1000
#define D_   512          // N of the GEMM
#define K2_  1024         // K of the GEMM
#define M_   (B_ * S_)    // 64000

#define TMM  128          // CTA M tile
#define KC   64           // K chunk (64 bf16 = 128B swizzled rows)
#define NCH  16           // K2_/KC

// ------------------------------------------------------------- device scratch
__device__ float g_hW[B_ * D_];
__device__ float g_logits[M_];
// W_bot pre-split (hi/lo bf16), transposed [n][k], SW128-swizzled per chunk
__device__ __align__(16) uint8_t g_wprep_hi[NCH * D_ * 128];
__device__ __align__(16) uint8_t g_wprep_lo[NCH * D_ * 128];
// enc pre-split to bf16 hi/lo, row-major [M_][K2_] (2KB rows)
__device__ __align__(16) uint8_t g_enc_hi[(size_t)M_ * K2_ * 2];
__device__ __align__(16) uint8_t g_enc_lo[(size_t)M_ * K2_ * 2];

// ---------------------------------------------------------------- smem layout
// A: [stage][hi/lo][128 rows][128B]   -> 2*2*16KB = 64KB
// B: [stage][hi/lo][256 rows][128B]   -> 2*2*32KB = 128KB
#define SA(st, lo)  ((st) * 32768 + (lo) * 16384)
#define SB(st, lo)  (65536 + (st) * 65536 + (lo) * 32768)
#define SM_SV   196608
#define SM_HW0  198656
#define SM_HW1  200704
#define SM_RS   202752
#define SM_TOTAL 203264

// ---------------------------------------------------------------- helpers
__device__ __forceinline__ uint32_t smem_u32(const void* p) {
    uint32_t a;
    asm("{ .reg .u64 t; cvta.to.shared.u64 t, %1; cvt.u32.u64 %0, t; }" : "=r"(a) : "l"(p));
    return a;
}
__host__ __device__ __forceinline__ uint32_t swz128(uint32_t off) {
    return off ^ ((off >> 3) & 0x70);
}
#define LDSM4(R, A)                                                             \
    asm volatile("ldmatrix.sync.aligned.m8n8.x4.shared.b16 {%0,%1,%2,%3}, [%4];" \
        : "=r"((R)[0]), "=r"((R)[1]), "=r"((R)[2]), "=r"((R)[3]) : "r"(A))
__device__ __forceinline__ void mma_bf16(float* c, const uint32_t* a, const uint32_t* b) {
    asm volatile("mma.sync.aligned.m16n8k16.row.col.f32.bf16.bf16.f32 "
        "{%0,%1,%2,%3},{%4,%5,%6,%7},{%8,%9},{%0,%1,%2,%3};"
        : "+f"(c[0]), "+f"(c[1]), "+f"(c[2]), "+f"(c[3])
        : "r"(a[0]), "r"(a[1]), "r"(a[2]), "r"(a[3]), "r"(b[0]), "r"(b[1]));
}
#define CP16(dst, src) \
    asm volatile("cp.async.cg.shared.global [%0], [%1], 16;" :: "r"(dst), "l"(src) : "memory")
#define CP_COMMIT() asm volatile("cp.async.commit_group;" ::: "memory")
#define CP_WAIT0()  asm volatile("cp.async.wait_group 0;" ::: "memory")
#define CP_WAIT1()  asm volatile("cp.async.wait_group 1;" ::: "memory")

// ---------------------------------------------------------------------------
// hW[b][n] = attn_b[n] + hidden[b] @ W_top[:,n]    grid(64,4) x 512
// 512 threads = 128 n-columns x 4 k-slices (k-parallel to kill LDG latency).
// ---------------------------------------------------------------------------
__global__ __launch_bounds__(512)
void hw_kernel(const float* __restrict__ hidden,
               const float* __restrict__ attn_w,
               const float* __restrict__ attn_b) {
    __shared__ float sh[D_];
    __shared__ float part[3][128];
    const int b  = blockIdx.x;
    const int nl = threadIdx.x & 127;
    const int ks = threadIdx.x >> 7;                // 0..3
    const int n  = blockIdx.y * 128 + nl;
    for (int i = threadIdx.x; i < D_; i += 512) sh[i] = hidden[b * D_ + i];
    __syncthreads();
    const int k0 = ks * 128;
    float a0 = 0.f, a1 = 0.f, a2 = 0.f, a3 = 0.f;
    #pragma unroll 8
    for (int k = k0; k < k0 + 128; k += 4) {
        a0 += sh[k + 0] * attn_w[(k + 0) * D_ + n];
        a1 += sh[k + 1] * attn_w[(k + 1) * D_ + n];
        a2 += sh[k + 2] * attn_w[(k + 2) * D_ + n];
        a3 += sh[k + 3] * attn_w[(k + 3) * D_ + n];
    }
    float acc = (a0 + a1) + (a2 + a3);
    if (ks) part[ks - 1][nl] = acc;
    __syncthreads();
    if (ks == 0)
        g_hW[b * D_ + n] = attn_b[n] + acc + part[0][nl] + part[1][nl] + part[2][nl];
}

// ---------------------------------------------------------------------------
// Split W_bot into bf16 hi/lo, transposed [n][k] + SW128-swizzled tile images.
// grid(16 chunks, 4 k-groups), block(512 = n)
// ---------------------------------------------------------------------------
__global__ void conv_w_kernel(const float* __restrict__ attn_w) {
    const int chunk = blockIdx.x;
    const int n = threadIdx.x;
    uint8_t* dh = g_wprep_hi + chunk * (D_ * 128);
    uint8_t* dl = g_wprep_lo + chunk * (D_ * 128);
    for (int kk = blockIdx.y * 16; kk < blockIdx.y * 16 + 16; kk++) {
        const int kg = D_ + chunk * KC + kk;
        float w = attn_w[(size_t)kg * D_ + n];
        __nv_bfloat16 hi = __float2bfloat16(w);
        __nv_bfloat16 lo = __float2bfloat16(w - __bfloat162float(hi));
        uint32_t sw = swz128((uint32_t)(n * 128 + kk * 2));
        *reinterpret_cast<uint16_t*>(dh + sw) = *reinterpret_cast<uint16_t*>(&hi);
        *reinterpret_cast<uint16_t*>(dl + sw) = *reinterpret_cast<uint16_t*>(&lo);
    }
}

// ---------------------------------------------------------------------------
// Split enc into bf16 hi/lo, plain row-major. grid(16000), block(256): 4 rows/CTA
// ---------------------------------------------------------------------------
__global__ __launch_bounds__(256)
void conv_enc_kernel(const float* __restrict__ enc) {
    const int r = blockIdx.x * 4 + (threadIdx.x >> 6);
    const int c = (threadIdx.x & 63) * 16;
    const float4* p = reinterpret_cast<const float4*>(enc + (size_t)r * K2_ + c);
    uint2* dh = reinterpret_cast<uint2*>(g_enc_hi + (size_t)r * (K2_ * 2) + c * 2);
    uint2* dl = reinterpret_cast<uint2*>(g_enc_lo + (size_t)r * (K2_ * 2) + c * 2);
    #pragma unroll
    for (int j = 0; j < 4; j++) {
        float4 f = p[j];
        __nv_bfloat16 h0 = __float2bfloat16(f.x);
        __nv_bfloat16 h1 = __float2bfloat16(f.y);
        __nv_bfloat16 h2 = __float2bfloat16(f.z);
        __nv_bfloat16 h3 = __float2bfloat16(f.w);
        __nv_bfloat16 l0 = __float2bfloat16(f.x - __bfloat162float(h0));
        __nv_bfloat16 l1 = __float2bfloat16(f.y - __bfloat162float(h1));
        __nv_bfloat16 l2 = __float2bfloat16(f.z - __bfloat162float(h2));
        __nv_bfloat16 l3 = __float2bfloat16(f.w - __bfloat162float(h3));
        __nv_bfloat162 hp0 = __halves2bfloat162(h0, h1);
        __nv_bfloat162 hp1 = __halves2bfloat162(h2, h3);
        __nv_bfloat162 lp0 = __halves2bfloat162(l0, l1);
        __nv_bfloat162 lp1 = __halves2bfloat162(l2, l3);
        dh[j] = make_uint2(*reinterpret_cast<uint32_t*>(&hp0),
                           *reinterpret_cast<uint32_t*>(&hp1));
        dl[j] = make_uint2(*reinterpret_cast<uint32_t*>(&lp0),
                           *reinterpret_cast<uint32_t*>(&lp1));
    }
}

// ---------------------------------------------------------------------------
// Main HMMA GEMM + tanh + v-dot.  grid(500), block(512) = 16 warps (4M x 4N)
// Pure cp.async -> ldmatrix -> mma pipeline; A pre-converted in gmem.
// ---------------------------------------------------------------------------
__global__ __launch_bounds__(512, 1)
void gemm_kernel(const float* __restrict__ v) {
    extern __shared__ __align__(1024) uint8_t smem[];
    const uint32_t sb = smem_u32(smem);
    const int tid  = threadIdx.x;
    const int wid  = tid >> 5;
    const int lane = tid & 31;
    const int wm   = wid >> 2;          // 0..3 (M quadrant, 32 rows)
    const int wn   = wid & 3;           // 0..3 (N quadrant, 64 cols)
    const int m0   = blockIdx.x * TMM;

    float* svp = reinterpret_cast<float*>(smem + SM_SV);
    float* hw0 = reinterpret_cast<float*>(smem + SM_HW0);
    float* hw1 = reinterpret_cast<float*>(smem + SM_HW1);
    float* rsm = reinterpret_cast<float*>(smem + SM_RS);

    const int b0 = m0 / S_;
    const int b1 = (m0 + TMM - 1) / S_;
    const int thr = (b0 + 1) * S_ - m0;   // rows >= thr belong to b1
    for (int i = tid; i < D_; i += 512) {
        svp[i] = v[i];
        hw0[i] = g_hW[b0 * D_ + i];
        hw1[i] = g_hW[b1 * D_ + i];
    }
    if (tid < TMM) rsm[tid] = 0.f;

    // ---- per-lane ldmatrix address components ------------------------------
    const int a_r16  = lane & 15;
    const uint32_t a_kext = (lane >> 4) << 4;
    uint32_t aoff[2], asw[2];
    #pragma unroll
    for (int ms = 0; ms < 2; ms++) {
        int r = wm * 32 + ms * 16 + a_r16;
        aoff[ms] = (uint32_t)r * 128;
        asw[ms]  = (uint32_t)(r & 7) << 4;
    }
    const int b_r16  = (lane & 7) | ((lane & 16) >> 1);
    const uint32_t b_kext = (lane & 8) << 1;
    uint32_t boff[4], bsw[4];
    #pragma unroll
    for (int np = 0; np < 4; np++) {
        int r = wn * 64 + np * 16 + b_r16;
        boff[np] = (uint32_t)r * 128;
        bsw[np]  = (uint32_t)(r & 7) << 4;
    }

    // ---- cp.async loader: A (hi/lo, 1024 pieces each) + B (pre-swizzled) ----
    const uint32_t ap0 = (uint32_t)tid;          // j=0 piece
    const uint32_t ap1 = (uint32_t)tid + 512;    // j=1 piece
    auto loadAB = [&](int pass, int chunk, int st) {
        #pragma unroll
        for (int j = 0; j < 2; j++) {
            uint32_t p = j ? ap1 : ap0;
            uint32_t row = p >> 3, c16 = p & 7;
            uint32_t dsto = row * 128 + ((c16 << 4) ^ ((row & 7) << 4));
            size_t   srco = (size_t)(m0 + row) * (K2_ * 2) + chunk * 128 + (c16 << 4);
            CP16(sb + SA(st, 0) + dsto, g_enc_hi + srco);
            CP16(sb + SA(st, 1) + dsto, g_enc_lo + srco);
        }
        const uint8_t* gh = g_wprep_hi + chunk * (D_ * 128) + pass * (256 * 128);
        const uint8_t* gl = g_wprep_lo + chunk * (D_ * 128) + pass * (256 * 128);
        #pragma unroll
        for (int j = 0; j < 4; j++) {
            uint32_t idx = (uint32_t)(tid + j * 512) * 16;
            CP16(sb + SB(st, 0) + idx, gh + idx);
            CP16(sb + SB(st, 1) + idx, gl + idx);
        }
        CP_COMMIT();
    };

    float acc[2][8][4];

    auto compute = [&](int st) {
        const uint32_t baseAh = sb + SA(st, 0);
        const uint32_t baseAl = sb + SA(st, 1);
        const uint32_t baseBh = sb + SB(st, 0);
        const uint32_t baseBl = sb + SB(st, 1);
        #pragma unroll
        for (int k16 = 0; k16 < 4; k16++) {
            const uint32_t ka = (uint32_t)(k16 * 32) + a_kext;
            const uint32_t kb = (uint32_t)(k16 * 32) + b_kext;
            uint32_t ah[2][4], al[2][4];
            #pragma unroll
            for (int ms = 0; ms < 2; ms++) {
                uint32_t o = aoff[ms] + (ka ^ asw[ms]);
                LDSM4(ah[ms], baseAh + o);
                LDSM4(al[ms], baseAl + o);
            }
            #pragma unroll
            for (int np = 0; np < 4; np++) {
                const uint32_t o = boff[np] + (kb ^ bsw[np]);
                uint32_t bh[4], bl[4];
                LDSM4(bh, baseBh + o);
                #pragma unroll
                for (int ms = 0; ms < 2; ms++) {
                    mma_bf16(acc[ms][np * 2 + 0], ah[ms], bh + 0);
                    mma_bf16(acc[ms][np * 2 + 1], ah[ms], bh + 2);
                    mma_bf16(acc[ms][np * 2 + 0], al[ms], bh + 0);
                    mma_bf16(acc[ms][np * 2 + 1], al[ms], bh + 2);
                }
                LDSM4(bl, baseBl + o);
                #pragma unroll
                for (int ms = 0; ms < 2; ms++) {
                    mma_bf16(acc[ms][np * 2 + 0], ah[ms], bl + 0);
                    mma_bf16(acc[ms][np * 2 + 1], ah[ms], bl + 2);
                }
            }
        }
    };

    const int gid = lane >> 2;
    const int tig = lane & 3;

    // ======================= two N-passes ====================================
    #pragma unroll 1
    for (int pass = 0; pass < 2; pass++) {
        #pragma unroll
        for (int ms = 0; ms < 2; ms++)
            #pragma unroll
            for (int ns = 0; ns < 8; ns++)
                #pragma unroll
                for (int c = 0; c < 4; c++) acc[ms][ns][c] = 0.f;

        loadAB(pass, 0, 0);

        #pragma unroll 1
        for (int i = 0; i < NCH; i++) {
            const int s = i & 1;
            const bool pf = (i + 1 < NCH);
            if (pf) { loadAB(pass, i + 1, s ^ 1); CP_WAIT1(); }
            else    { CP_WAIT0(); }
            __syncthreads();           // stage s visible to all
            compute(s);
            __syncthreads();           // all readers of stage s done
        }

        // epilogue: x = acc + hW, rowsum += v * tanh(x)
        #pragma unroll
        for (int ms = 0; ms < 2; ms++) {
            #pragma unroll
            for (int ch = 0; ch < 2; ch++) {
                const int r = wm * 32 + ms * 16 + ch * 8 + gid;
                const float* hwrow = (r >= thr) ? hw1 : hw0;
                float rs = 0.f;
                #pragma unroll
                for (int ns = 0; ns < 8; ns++) {
                    const int n = pass * 256 + wn * 64 + ns * 8 + tig * 2;
                    float x0 = acc[ms][ns][ch * 2 + 0] + hwrow[n];
                    float x1 = acc[ms][ns][ch * 2 + 1] + hwrow[n + 1];
                    rs += svp[n] * tanhf(x0) + svp[n + 1] * tanhf(x1);
                }
                rs += __shfl_xor_sync(0xffffffffu, rs, 1);
                rs += __shfl_xor_sync(0xffffffffu, rs, 2);
                if (tig == 0) atomicAdd(&rsm[r], rs);
            }
        }
    }

    __syncthreads();
    if (tid < TMM) g_logits[m0 + tid] = rsm[tid];
}

// ---------------------------------------------------------------------------
// softmax over S per batch. grid(64), block(256)
// ---------------------------------------------------------------------------
__global__ void softmax_kernel(float* __restrict__ out) {
    __shared__ float red[256];
    const int b = blockIdx.x;
    const int t = threadIdx.x;
    const float* row = g_logits + b * S_;
    float* orow = out + b * S_;

    float mx = -INFINITY;
    for (int i = t; i < S_; i += 256) mx = fmaxf(mx, row[i]);
    red[t] = mx;
    __syncthreads();
    for (int off = 128; off > 0; off >>= 1) {
        if (t < off) red[t] = fmaxf(red[t], red[t + off]);
        __syncthreads();
    }
    mx = red[0];
    __syncthreads();

    float sum = 0.f;
    for (int i = t; i < S_; i += 256) {
        float e = expf(row[i] - mx);
        orow[i] = e;
        sum += e;
    }
    red[t] = sum;
    __syncthreads();
    for (int off = 128; off > 0; off >>= 1) {
        if (t < off) red[t] += red[t + off];
        __syncthreads();
    }
    const float inv = 1.f / red[0];
    __syncthreads();
    for (int i = t; i < S_; i += 256) orow[i] *= inv;
}

// ---------------------------------------------------------------------------
extern "C" void kernel_launch(void* const* d_in, const int* in_sizes, int n_in,
                              void* d_out, int out_size) {
    const float* hidden = (const float*)d_in[0];   // [64, 512]
    const float* enc    = (const float*)d_in[1];   // [64, 1000, 1024]
    const float* attn_w = (const float*)d_in[2];   // [1536, 512]
    const float* attn_b = (const float*)d_in[3];   // [512]
    const float* v      = (const float*)d_in[4];   // [512]
    float* out = (float*)d_out;                    // [64, 1000]

    cudaFuncSetAttribute(gemm_kernel,
                         cudaFuncAttributeMaxDynamicSharedMemorySize, SM_TOTAL);

    conv_w_kernel<<<dim3(NCH, 4), D_>>>(attn_w);
    hw_kernel<<<dim3(B_, 4), 512>>>(hidden, attn_w, attn_b);
    conv_enc_kernel<<<M_ / 4, 256>>>(enc);
    gemm_kernel<<<M_ / TMM, 512, SM_TOTAL>>>(v);
    softmax_kernel<<<B_, 256>>>(out);
}

// round 9
// speedup vs baseline: 3.1318x; 1.0336x over previous
#include <cuda_runtime.h>
#include <cuda_bf16.h>
#include <math.h>
#include <stdint.h>

// ---------------------------------------------------------------- constants
#define B_   64
#define S_   1000
#define D_   512          // N of the GEMM
#define K2_  1024         // K of the GEMM
#define M_   (B_ * S_)    // 64000

#define TMM  64           // CTA M tile (small -> 2 CTAs/SM)
#define KC   64           // K chunk (64 bf16 = 128B swizzled rows)
#define NCH  16           // K2_/KC
#define NPASS 4           // N passes of 128 cols

// ------------------------------------------------------------- device scratch
__device__ float g_hW[B_ * D_];
__device__ float g_logits[M_];
// W_bot pre-split (hi/lo bf16), transposed [n][k], SW128-swizzled per chunk
__device__ __align__(16) uint8_t g_wprep_hi[NCH * D_ * 128];
__device__ __align__(16) uint8_t g_wprep_lo[NCH * D_ * 128];
// enc pre-split to bf16 hi/lo, row-major [M_][K2_] (2KB rows), NOT swizzled
__device__ __align__(16) uint8_t g_enc_hi[(size_t)M_ * K2_ * 2];
__device__ __align__(16) uint8_t g_enc_lo[(size_t)M_ * K2_ * 2];

// ---------------------------------------------------------------- smem layout
// A: [stage][plane][64 rows][128B]  -> 4 x 8KB  = 32KB
// B: [stage][plane][128 rows][128B] -> 4 x 16KB = 64KB
#define SA(st, pl)  ((st) * 16384 + (pl) * 8192)
#define SB(st, pl)  (32768 + (st) * 32768 + (pl) * 16384)
#define SM_SV   98304       // 512 f32
#define SM_HW0  100352      // 512 f32
#define SM_HW1  102400      // 512 f32
#define SM_RS   104448      // 64 f32
#define SM_TOTAL 104704

// ---------------------------------------------------------------- helpers
__device__ __forceinline__ uint32_t smem_u32(const void* p) {
    uint32_t a;
    asm("{ .reg .u64 t; cvta.to.shared.u64 t, %1; cvt.u32.u64 %0, t; }" : "=r"(a) : "l"(p));
    return a;
}
__host__ __device__ __forceinline__ uint32_t swz128(uint32_t off) {
    return off ^ ((off >> 3) & 0x70);
}
#define LDSM4(R, A)                                                             \
    asm volatile("ldmatrix.sync.aligned.m8n8.x4.shared.b16 {%0,%1,%2,%3}, [%4];" \
        : "=r"((R)[0]), "=r"((R)[1]), "=r"((R)[2]), "=r"((R)[3]) : "r"(A))
__device__ __forceinline__ void mma_bf16(float* c, const uint32_t* a, const uint32_t* b) {
    asm volatile("mma.sync.aligned.m16n8k16.row.col.f32.bf16.bf16.f32 "
        "{%0,%1,%2,%3},{%4,%5,%6,%7},{%8,%9},{%0,%1,%2,%3};"
        : "+f"(c[0]), "+f"(c[1]), "+f"(c[2]), "+f"(c[3])
        : "r"(a[0]), "r"(a[1]), "r"(a[2]), "r"(a[3]), "r"(b[0]), "r"(b[1]));
}
#define CP16(dst, src) \
    asm volatile("cp.async.cg.shared.global [%0], [%1], 16;" :: "r"(dst), "l"(src) : "memory")
#define CP_COMMIT() asm volatile("cp.async.commit_group;" ::: "memory")
#define CP_WAIT0()  asm volatile("cp.async.wait_group 0;" ::: "memory")
#define CP_WAIT1()  asm volatile("cp.async.wait_group 1;" ::: "memory")

// ---------------------------------------------------------------------------
// hW[b][n] = attn_b[n] + hidden[b] @ W_top[:,n]    grid(64,4) x 512
// ---------------------------------------------------------------------------
__global__ __launch_bounds__(512)
void hw_kernel(const float* __restrict__ hidden,
               const float* __restrict__ attn_w,
               const float* __restrict__ attn_b) {
    __shared__ float sh[D_];
    __shared__ float part[3][128];
    const int b  = blockIdx.x;
    const int nl = threadIdx.x & 127;
    const int ks = threadIdx.x >> 7;                // 0..3
    const int n  = blockIdx.y * 128 + nl;
    for (int i = threadIdx.x; i < D_; i += 512) sh[i] = hidden[b * D_ + i];
    __syncthreads();
    const int k0 = ks * 128;
    float a0 = 0.f, a1 = 0.f, a2 = 0.f, a3 = 0.f;
    #pragma unroll 8
    for (int k = k0; k < k0 + 128; k += 4) {
        a0 += sh[k + 0] * attn_w[(k + 0) * D_ + n];
        a1 += sh[k + 1] * attn_w[(k + 1) * D_ + n];
        a2 += sh[k + 2] * attn_w[(k + 2) * D_ + n];
        a3 += sh[k + 3] * attn_w[(k + 3) * D_ + n];
    }
    float acc = (a0 + a1) + (a2 + a3);
    if (ks) part[ks - 1][nl] = acc;
    __syncthreads();
    if (ks == 0)
        g_hW[b * D_ + n] = attn_b[n] + acc + part[0][nl] + part[1][nl] + part[2][nl];
}

// ---------------------------------------------------------------------------
// Split W_bot into bf16 hi/lo, transposed [n][k] + SW128-swizzled tile images.
// ---------------------------------------------------------------------------
__global__ void conv_w_kernel(const float* __restrict__ attn_w) {
    const int chunk = blockIdx.x;
    const int n = threadIdx.x;
    uint8_t* dh = g_wprep_hi + chunk * (D_ * 128);
    uint8_t* dl = g_wprep_lo + chunk * (D_ * 128);
    for (int kk = blockIdx.y * 16; kk < blockIdx.y * 16 + 16; kk++) {
        const int kg = D_ + chunk * KC + kk;
        float w = attn_w[(size_t)kg * D_ + n];
        __nv_bfloat16 hi = __float2bfloat16(w);
        __nv_bfloat16 lo = __float2bfloat16(w - __bfloat162float(hi));
        uint32_t sw = swz128((uint32_t)(n * 128 + kk * 2));
        *reinterpret_cast<uint16_t*>(dh + sw) = *reinterpret_cast<uint16_t*>(&hi);
        *reinterpret_cast<uint16_t*>(dl + sw) = *reinterpret_cast<uint16_t*>(&lo);
    }
}

// ---------------------------------------------------------------------------
// Split enc into bf16 hi/lo, plain row-major. grid(16000), block(256)
// ---------------------------------------------------------------------------
__global__ __launch_bounds__(256)
void conv_enc_kernel(const float* __restrict__ enc) {
    const int r = blockIdx.x * 4 + (threadIdx.x >> 6);
    const int c = (threadIdx.x & 63) * 16;
    const float4* p = reinterpret_cast<const float4*>(enc + (size_t)r * K2_ + c);
    uint2* dh = reinterpret_cast<uint2*>(g_enc_hi + (size_t)r * (K2_ * 2) + c * 2);
    uint2* dl = reinterpret_cast<uint2*>(g_enc_lo + (size_t)r * (K2_ * 2) + c * 2);
    #pragma unroll
    for (int j = 0; j < 4; j++) {
        float4 f = p[j];
        __nv_bfloat16 h0 = __float2bfloat16(f.x);
        __nv_bfloat16 h1 = __float2bfloat16(f.y);
        __nv_bfloat16 h2 = __float2bfloat16(f.z);
        __nv_bfloat16 h3 = __float2bfloat16(f.w);
        __nv_bfloat16 l0 = __float2bfloat16(f.x - __bfloat162float(h0));
        __nv_bfloat16 l1 = __float2bfloat16(f.y - __bfloat162float(h1));
        __nv_bfloat16 l2 = __float2bfloat16(f.z - __bfloat162float(h2));
        __nv_bfloat16 l3 = __float2bfloat16(f.w - __bfloat162float(h3));
        __nv_bfloat162 hp0 = __halves2bfloat162(h0, h1);
        __nv_bfloat162 hp1 = __halves2bfloat162(h2, h3);
        __nv_bfloat162 lp0 = __halves2bfloat162(l0, l1);
        __nv_bfloat162 lp1 = __halves2bfloat162(l2, l3);
        dh[j] = make_uint2(*reinterpret_cast<uint32_t*>(&hp0),
                           *reinterpret_cast<uint32_t*>(&hp1));
        dl[j] = make_uint2(*reinterpret_cast<uint32_t*>(&lp0),
                           *reinterpret_cast<uint32_t*>(&lp1));
    }
}

// ---------------------------------------------------------------------------
// Main HMMA GEMM + tanh + v-dot.  grid(1000), block(512), 2 CTAs/SM.
// 16 warps = 4M(16 rows) x 4N(32 cols); 4 N-passes of 128 cols.
// ---------------------------------------------------------------------------
__global__ __launch_bounds__(512, 2)
void gemm_kernel(const float* __restrict__ v) {
    extern __shared__ __align__(1024) uint8_t smem[];
    const uint32_t sb = smem_u32(smem);
    const int tid  = threadIdx.x;
    const int wid  = tid >> 5;
    const int lane = tid & 31;
    const int wm   = wid >> 2;          // 0..3 (16 M rows each)
    const int wn   = wid & 3;           // 0..3 (32 N cols each)
    const int m0   = blockIdx.x * TMM;

    float* svp = reinterpret_cast<float*>(smem + SM_SV);
    float* hw0 = reinterpret_cast<float*>(smem + SM_HW0);
    float* hw1 = reinterpret_cast<float*>(smem + SM_HW1);
    float* rsm = reinterpret_cast<float*>(smem + SM_RS);

    const int b0 = m0 / S_;
    const int b1 = (m0 + TMM - 1) / S_;
    const int thr = (b0 + 1) * S_ - m0;   // rows >= thr belong to b1
    for (int i = tid; i < D_; i += 512) {
        svp[i] = v[i];
        hw0[i] = g_hW[b0 * D_ + i];
        hw1[i] = g_hW[b1 * D_ + i];
    }
    if (tid < TMM) rsm[tid] = 0.f;

    // ---- per-lane ldmatrix address components ------------------------------
    // A frag (16 rows x 32B): lanes 0-15 rows, lanes>=16 k+16B
    const int a_r16 = lane & 15;
    const uint32_t a_kext = (lane >> 4) << 4;
    const int a_row = wm * 16 + a_r16;
    const uint32_t aoff = (uint32_t)a_row * 128;
    const uint32_t a_swz = (uint32_t)(a_row & 7) << 4;
    // B frag (16 cols x 32B): lanes {0-7,16-23} rows, bit3 -> k+16B
    const int b_r16 = (lane & 7) | ((lane & 16) >> 1);
    const uint32_t b_kext = (lane & 8) << 1;
    uint32_t boff[2], bsw[2];
    #pragma unroll
    for (int np = 0; np < 2; np++) {
        int r = wn * 32 + np * 16 + b_r16;
        boff[np] = (uint32_t)r * 128;
        bsw[np]  = (uint32_t)(r & 7) << 4;
    }

    // ---- cp.async loader ----------------------------------------------------
    // A: 64 rows x 8 c16 = 512 pieces/plane (1 per thread); src LINEAR -> swizzle on store
    // B: 128 rows x 8 c16 = 1024 pieces/plane (2 per thread); src PRE-SWIZZLED -> copy STRAIGHT
    auto loadAB = [&](int pass, int chunk, int st) {
        {
            uint32_t p = (uint32_t)tid;
            uint32_t row = p >> 3, c16 = p & 7;
            uint32_t dsto = row * 128 + ((c16 << 4) ^ ((row & 7) << 4));
            size_t   srco = (size_t)(m0 + row) * (K2_ * 2) + chunk * 128 + (c16 << 4);
            CP16(sb + SA(st, 0) + dsto, g_enc_hi + srco);
            CP16(sb + SA(st, 1) + dsto, g_enc_lo + srco);
        }
        const uint8_t* gh = g_wprep_hi + chunk * (D_ * 128) + pass * (128 * 128);
        const uint8_t* gl = g_wprep_lo + chunk * (D_ * 128) + pass * (128 * 128);
        #pragma unroll
        for (int j = 0; j < 2; j++) {
            uint32_t idx = (uint32_t)(tid + j * 512) * 16;   // straight copy keeps swizzle
            CP16(sb + SB(st, 0) + idx, gh + idx);
            CP16(sb + SB(st, 1) + idx, gl + idx);
        }
        CP_COMMIT();
    };

    float acc[4][4];   // 4 n8-fragments x 4

    auto compute = [&](int st) {
        const uint32_t baseAh = sb + SA(st, 0);
        const uint32_t baseAl = sb + SA(st, 1);
        const uint32_t baseBh = sb + SB(st, 0);
        const uint32_t baseBl = sb + SB(st, 1);
        #pragma unroll
        for (int k16 = 0; k16 < 4; k16++) {
            const uint32_t ka = (uint32_t)(k16 * 32) + a_kext;
            const uint32_t kb = (uint32_t)(k16 * 32) + b_kext;
            uint32_t ah[4], al[4];
            uint32_t ao = aoff + (ka ^ a_swz);
            LDSM4(ah, baseAh + ao);
            LDSM4(al, baseAl + ao);
            #pragma unroll
            for (int np = 0; np < 2; np++) {
                const uint32_t o = boff[np] + (kb ^ bsw[np]);
                uint32_t bh[4], bl[4];
                LDSM4(bh, baseBh + o);
                mma_bf16(acc[np * 2 + 0], ah, bh + 0);
                mma_bf16(acc[np * 2 + 1], ah, bh + 2);
                mma_bf16(acc[np * 2 + 0], al, bh + 0);
                mma_bf16(acc[np * 2 + 1], al, bh + 2);
                LDSM4(bl, baseBl + o);
                mma_bf16(acc[np * 2 + 0], ah, bl + 0);
                mma_bf16(acc[np * 2 + 1], ah, bl + 2);
            }
        }
    };

    const int gid = lane >> 2;
    const int tig = lane & 3;

    // ======================= four N-passes (128 cols each) ==================
    #pragma unroll 1
    for (int pass = 0; pass < NPASS; pass++) {
        #pragma unroll
        for (int f = 0; f < 4; f++)
            #pragma unroll
            for (int c = 0; c < 4; c++) acc[f][c] = 0.f;

        loadAB(pass, 0, 0);

        #pragma unroll 1
        for (int i = 0; i < NCH; i++) {
            const int s = i & 1;
            const bool pf = (i + 1 < NCH);
            if (pf) { loadAB(pass, i + 1, s ^ 1); CP_WAIT1(); }
            else    { CP_WAIT0(); }
            __syncthreads();
            compute(s);
            __syncthreads();
        }

        // epilogue: x = acc + hW, rowsum += v * tanh(x)
        #pragma unroll
        for (int ch = 0; ch < 2; ch++) {
            const int r = wm * 16 + ch * 8 + gid;
            const float* hwrow = (r >= thr) ? hw1 : hw0;
            float rs = 0.f;
            #pragma unroll
            for (int f = 0; f < 4; f++) {
                const int n = pass * 128 + wn * 32 + f * 8 + tig * 2;
                float x0 = acc[f][ch * 2 + 0] + hwrow[n];
                float x1 = acc[f][ch * 2 + 1] + hwrow[n + 1];
                rs += svp[n] * tanhf(x0) + svp[n + 1] * tanhf(x1);
            }
            rs += __shfl_xor_sync(0xffffffffu, rs, 1);
            rs += __shfl_xor_sync(0xffffffffu, rs, 2);
            if (tig == 0) atomicAdd(&rsm[r], rs);
        }
    }

    __syncthreads();
    if (tid < TMM) g_logits[m0 + tid] = rsm[tid];
}

// ---------------------------------------------------------------------------
// softmax over S per batch. grid(64), block(256)
// ---------------------------------------------------------------------------
__global__ void softmax_kernel(float* __restrict__ out) {
    __shared__ float red[256];
    const int b = blockIdx.x;
    const int t = threadIdx.x;
    const float* row = g_logits + b * S_;
    float* orow = out + b * S_;

    float mx = -INFINITY;
    for (int i = t; i < S_; i += 256) mx = fmaxf(mx, row[i]);
    red[t] = mx;
    __syncthreads();
    for (int off = 128; off > 0; off >>= 1) {
        if (t < off) red[t] = fmaxf(red[t], red[t + off]);
        __syncthreads();
    }
    mx = red[0];
    __syncthreads();

    float sum = 0.f;
    for (int i = t; i < S_; i += 256) {
        float e = expf(row[i] - mx);
        orow[i] = e;
        sum += e;
    }
    red[t] = sum;
    __syncthreads();
    for (int off = 128; off > 0; off >>= 1) {
        if (t < off) red[t] += red[t + off];
        __syncthreads();
    }
    const float inv = 1.f / red[0];
    __syncthreads();
    for (int i = t; i < S_; i += 256) orow[i] *= inv;
}

// ---------------------------------------------------------------------------
extern "C" void kernel_launch(void* const* d_in, const int* in_sizes, int n_in,
                              void* d_out, int out_size) {
    const float* hidden = (const float*)d_in[0];   // [64, 512]
    const float* enc    = (const float*)d_in[1];   // [64, 1000, 1024]
    const float* attn_w = (const float*)d_in[2];   // [1536, 512]
    const float* attn_b = (const float*)d_in[3];   // [512]
    const float* v      = (const float*)d_in[4];   // [512]
    float* out = (float*)d_out;                    // [64, 1000]

    cudaFuncSetAttribute(gemm_kernel,
                         cudaFuncAttributeMaxDynamicSharedMemorySize, SM_TOTAL);

    conv_w_kernel<<<dim3(NCH, 4), D_>>>(attn_w);
    hw_kernel<<<dim3(B_, 4), 512>>>(hidden, attn_w, attn_b);
    conv_enc_kernel<<<M_ / 4, 256>>>(enc);
    gemm_kernel<<<M_ / TMM, 512, SM_TOTAL>>>(v);
    softmax_kernel<<<B_, 256>>>(out);
}

// round 10
// speedup vs baseline: 3.2631x; 1.0419x over previous
#include <cuda_runtime.h>
#include <cuda_bf16.h>
#include <math.h>
#include <stdint.h>

// ---------------------------------------------------------------- constants
#define B_   64
#define S_   1000
#define D_   512          // N of the GEMM
#define K2_  1024         // K of the GEMM
#define M_   (B_ * S_)    // 64000

#define TMM  64           // CTA M tile (small -> 2 CTAs/SM)
#define KC   64           // K chunk (64 bf16 = 128B swizzled rows)
#define NCH  16           // K2_/KC
#define NPASS 4           // N passes of 128 cols
#define NT   256          // threads per CTA (8 warps = 2M x 4N)

// ------------------------------------------------------------- device scratch
__device__ float g_hW[B_ * D_];
__device__ float g_logits[M_];
// W_bot pre-split (hi/lo bf16), transposed [n][k], SW128-swizzled per chunk
__device__ __align__(16) uint8_t g_wprep_hi[NCH * D_ * 128];
__device__ __align__(16) uint8_t g_wprep_lo[NCH * D_ * 128];
// enc pre-split to bf16 hi/lo, row-major [M_][K2_] (2KB rows), NOT swizzled
__device__ __align__(16) uint8_t g_enc_hi[(size_t)M_ * K2_ * 2];
__device__ __align__(16) uint8_t g_enc_lo[(size_t)M_ * K2_ * 2];

// ---------------------------------------------------------------- smem layout
// A: [stage][plane][64 rows][128B]  -> 4 x 8KB  = 32KB
// B: [stage][plane][128 rows][128B] -> 4 x 16KB = 64KB
#define SA(st, pl)  ((st) * 16384 + (pl) * 8192)
#define SB(st, pl)  (32768 + (st) * 32768 + (pl) * 16384)
#define SM_SV   98304       // 512 f32
#define SM_HW0  100352      // 512 f32
#define SM_HW1  102400      // 512 f32
#define SM_RS   104448      // 64 f32
#define SM_TOTAL 104704

// ---------------------------------------------------------------- helpers
__device__ __forceinline__ uint32_t smem_u32(const void* p) {
    uint32_t a;
    asm("{ .reg .u64 t; cvta.to.shared.u64 t, %1; cvt.u32.u64 %0, t; }" : "=r"(a) : "l"(p));
    return a;
}
__host__ __device__ __forceinline__ uint32_t swz128(uint32_t off) {
    return off ^ ((off >> 3) & 0x70);
}
#define LDSM4(R, A)                                                             \
    asm volatile("ldmatrix.sync.aligned.m8n8.x4.shared.b16 {%0,%1,%2,%3}, [%4];" \
        : "=r"((R)[0]), "=r"((R)[1]), "=r"((R)[2]), "=r"((R)[3]) : "r"(A))
__device__ __forceinline__ void mma_bf16(float* c, const uint32_t* a, const uint32_t* b) {
    asm volatile("mma.sync.aligned.m16n8k16.row.col.f32.bf16.bf16.f32 "
        "{%0,%1,%2,%3},{%4,%5,%6,%7},{%8,%9},{%0,%1,%2,%3};"
        : "+f"(c[0]), "+f"(c[1]), "+f"(c[2]), "+f"(c[3])
        : "r"(a[0]), "r"(a[1]), "r"(a[2]), "r"(a[3]), "r"(b[0]), "r"(b[1]));
}
#define CP16(dst, src) \
    asm volatile("cp.async.cg.shared.global [%0], [%1], 16;" :: "r"(dst), "l"(src) : "memory")
#define CP_COMMIT() asm volatile("cp.async.commit_group;" ::: "memory")
#define CP_WAIT0()  asm volatile("cp.async.wait_group 0;" ::: "memory")
#define CP_WAIT1()  asm volatile("cp.async.wait_group 1;" ::: "memory")

// ---------------------------------------------------------------------------
// hW[b][n] = attn_b[n] + hidden[b] @ W_top[:,n]    grid(64,4) x 512
// ---------------------------------------------------------------------------
__global__ __launch_bounds__(512)
void hw_kernel(const float* __restrict__ hidden,
               const float* __restrict__ attn_w,
               const float* __restrict__ attn_b) {
    __shared__ float sh[D_];
    __shared__ float part[3][128];
    const int b  = blockIdx.x;
    const int nl = threadIdx.x & 127;
    const int ks = threadIdx.x >> 7;                // 0..3
    const int n  = blockIdx.y * 128 + nl;
    for (int i = threadIdx.x; i < D_; i += 512) sh[i] = hidden[b * D_ + i];
    __syncthreads();
    const int k0 = ks * 128;
    float a0 = 0.f, a1 = 0.f, a2 = 0.f, a3 = 0.f;
    #pragma unroll 8
    for (int k = k0; k < k0 + 128; k += 4) {
        a0 += sh[k + 0] * attn_w[(k + 0) * D_ + n];
        a1 += sh[k + 1] * attn_w[(k + 1) * D_ + n];
        a2 += sh[k + 2] * attn_w[(k + 2) * D_ + n];
        a3 += sh[k + 3] * attn_w[(k + 3) * D_ + n];
    }
    float acc = (a0 + a1) + (a2 + a3);
    if (ks) part[ks - 1][nl] = acc;
    __syncthreads();
    if (ks == 0)
        g_hW[b * D_ + n] = attn_b[n] + acc + part[0][nl] + part[1][nl] + part[2][nl];
}

// ---------------------------------------------------------------------------
// Split W_bot into bf16 hi/lo, transposed [n][k] + SW128-swizzled tile images.
// ---------------------------------------------------------------------------
__global__ void conv_w_kernel(const float* __restrict__ attn_w) {
    const int chunk = blockIdx.x;
    const int n = threadIdx.x;
    uint8_t* dh = g_wprep_hi + chunk * (D_ * 128);
    uint8_t* dl = g_wprep_lo + chunk * (D_ * 128);
    for (int kk = blockIdx.y * 16; kk < blockIdx.y * 16 + 16; kk++) {
        const int kg = D_ + chunk * KC + kk;
        float w = attn_w[(size_t)kg * D_ + n];
        __nv_bfloat16 hi = __float2bfloat16(w);
        __nv_bfloat16 lo = __float2bfloat16(w - __bfloat162float(hi));
        uint32_t sw = swz128((uint32_t)(n * 128 + kk * 2));
        *reinterpret_cast<uint16_t*>(dh + sw) = *reinterpret_cast<uint16_t*>(&hi);
        *reinterpret_cast<uint16_t*>(dl + sw) = *reinterpret_cast<uint16_t*>(&lo);
    }
}

// ---------------------------------------------------------------------------
// Split enc into bf16 hi/lo, plain row-major. grid(16000), block(256)
// ---------------------------------------------------------------------------
__global__ __launch_bounds__(256)
void conv_enc_kernel(const float* __restrict__ enc) {
    const int r = blockIdx.x * 4 + (threadIdx.x >> 6);
    const int c = (threadIdx.x & 63) * 16;
    const float4* p = reinterpret_cast<const float4*>(enc + (size_t)r * K2_ + c);
    uint2* dh = reinterpret_cast<uint2*>(g_enc_hi + (size_t)r * (K2_ * 2) + c * 2);
    uint2* dl = reinterpret_cast<uint2*>(g_enc_lo + (size_t)r * (K2_ * 2) + c * 2);
    #pragma unroll
    for (int j = 0; j < 4; j++) {
        float4 f = p[j];
        __nv_bfloat16 h0 = __float2bfloat16(f.x);
        __nv_bfloat16 h1 = __float2bfloat16(f.y);
        __nv_bfloat16 h2 = __float2bfloat16(f.z);
        __nv_bfloat16 h3 = __float2bfloat16(f.w);
        __nv_bfloat16 l0 = __float2bfloat16(f.x - __bfloat162float(h0));
        __nv_bfloat16 l1 = __float2bfloat16(f.y - __bfloat162float(h1));
        __nv_bfloat16 l2 = __float2bfloat16(f.z - __bfloat162float(h2));
        __nv_bfloat16 l3 = __float2bfloat16(f.w - __bfloat162float(h3));
        __nv_bfloat162 hp0 = __halves2bfloat162(h0, h1);
        __nv_bfloat162 hp1 = __halves2bfloat162(h2, h3);
        __nv_bfloat162 lp0 = __halves2bfloat162(l0, l1);
        __nv_bfloat162 lp1 = __halves2bfloat162(l2, l3);
        dh[j] = make_uint2(*reinterpret_cast<uint32_t*>(&hp0),
                           *reinterpret_cast<uint32_t*>(&hp1));
        dl[j] = make_uint2(*reinterpret_cast<uint32_t*>(&lp0),
                           *reinterpret_cast<uint32_t*>(&lp1));
    }
}

// ---------------------------------------------------------------------------
// Main HMMA GEMM + tanh + v-dot.  grid(1000), block(256), 2 CTAs/SM.
// 8 warps = 2M(32 rows) x 4N(32 cols); warp tile 32x32 -> LDSM:MMA = 1:3.
// ---------------------------------------------------------------------------
__global__ __launch_bounds__(NT, 2)
void gemm_kernel(const float* __restrict__ v) {
    extern __shared__ __align__(1024) uint8_t smem[];
    const uint32_t sb = smem_u32(smem);
    const int tid  = threadIdx.x;
    const int wid  = tid >> 5;
    const int lane = tid & 31;
    const int wm   = wid >> 2;          // 0..1 (32 M rows each)
    const int wn   = wid & 3;           // 0..3 (32 N cols each)
    const int m0   = blockIdx.x * TMM;

    float* svp = reinterpret_cast<float*>(smem + SM_SV);
    float* hw0 = reinterpret_cast<float*>(smem + SM_HW0);
    float* hw1 = reinterpret_cast<float*>(smem + SM_HW1);
    float* rsm = reinterpret_cast<float*>(smem + SM_RS);

    const int b0 = m0 / S_;
    const int b1 = (m0 + TMM - 1) / S_;
    const int thr = (b0 + 1) * S_ - m0;   // rows >= thr belong to b1
    for (int i = tid; i < D_; i += NT) {
        svp[i] = v[i];
        hw0[i] = g_hW[b0 * D_ + i];
        hw1[i] = g_hW[b1 * D_ + i];
    }
    if (tid < TMM) rsm[tid] = 0.f;

    // ---- per-lane ldmatrix address components ------------------------------
    // A frags (2 per warp, 16 rows x 32B each): lanes 0-15 rows, lanes>=16 k+16B
    const int a_r16 = lane & 15;
    const uint32_t a_kext = (lane >> 4) << 4;
    uint32_t aoff[2], aswz[2];
    #pragma unroll
    for (int ms = 0; ms < 2; ms++) {
        int r = wm * 32 + ms * 16 + a_r16;
        aoff[ms] = (uint32_t)r * 128;
        aswz[ms] = (uint32_t)(r & 7) << 4;
    }
    // B frags (2 per warp, 16 cols x 32B): lanes {0-7,16-23} rows, bit3 -> k+16B
    const int b_r16 = (lane & 7) | ((lane & 16) >> 1);
    const uint32_t b_kext = (lane & 8) << 1;
    uint32_t boff[2], bsw[2];
    #pragma unroll
    for (int np = 0; np < 2; np++) {
        int r = wn * 32 + np * 16 + b_r16;
        boff[np] = (uint32_t)r * 128;
        bsw[np]  = (uint32_t)(r & 7) << 4;
    }

    // ---- cp.async loader ----------------------------------------------------
    // A: 512 pieces/plane (2/thread); src LINEAR -> swizzle on store
    // B: 1024 pieces/plane (4/thread); src PRE-SWIZZLED -> copy STRAIGHT
    auto loadAB = [&](int pass, int chunk, int st) {
        #pragma unroll
        for (int j = 0; j < 2; j++) {
            uint32_t p = (uint32_t)tid + j * NT;
            uint32_t row = p >> 3, c16 = p & 7;
            uint32_t dsto = row * 128 + ((c16 << 4) ^ ((row & 7) << 4));
            size_t   srco = (size_t)(m0 + row) * (K2_ * 2) + chunk * 128 + (c16 << 4);
            CP16(sb + SA(st, 0) + dsto, g_enc_hi + srco);
            CP16(sb + SA(st, 1) + dsto, g_enc_lo + srco);
        }
        const uint8_t* gh = g_wprep_hi + chunk * (D_ * 128) + pass * (128 * 128);
        const uint8_t* gl = g_wprep_lo + chunk * (D_ * 128) + pass * (128 * 128);
        #pragma unroll
        for (int j = 0; j < 4; j++) {
            uint32_t idx = (uint32_t)(tid + j * NT) * 16;   // straight copy keeps swizzle
            CP16(sb + SB(st, 0) + idx, gh + idx);
            CP16(sb + SB(st, 1) + idx, gl + idx);
        }
        CP_COMMIT();
    };

    float acc[2][4][4];   // [ms][np*2+half][4]

    auto compute = [&](int st) {
        const uint32_t baseAh = sb + SA(st, 0);
        const uint32_t baseAl = sb + SA(st, 1);
        const uint32_t baseBh = sb + SB(st, 0);
        const uint32_t baseBl = sb + SB(st, 1);
        #pragma unroll
        for (int k16 = 0; k16 < 4; k16++) {
            const uint32_t ka = (uint32_t)(k16 * 32) + a_kext;
            const uint32_t kb = (uint32_t)(k16 * 32) + b_kext;
            uint32_t ah[2][4], al[2][4];
            #pragma unroll
            for (int ms = 0; ms < 2; ms++) {
                uint32_t o = aoff[ms] + (ka ^ aswz[ms]);
                LDSM4(ah[ms], baseAh + o);
                LDSM4(al[ms], baseAl + o);
            }
            #pragma unroll
            for (int np = 0; np < 2; np++) {
                const uint32_t o = boff[np] + (kb ^ bsw[np]);
                uint32_t bh[4], bl[4];
                LDSM4(bh, baseBh + o);
                #pragma unroll
                for (int ms = 0; ms < 2; ms++) {
                    mma_bf16(acc[ms][np * 2 + 0], ah[ms], bh + 0);
                    mma_bf16(acc[ms][np * 2 + 1], ah[ms], bh + 2);
                    mma_bf16(acc[ms][np * 2 + 0], al[ms], bh + 0);
                    mma_bf16(acc[ms][np * 2 + 1], al[ms], bh + 2);
                }
                LDSM4(bl, baseBl + o);
                #pragma unroll
                for (int ms = 0; ms < 2; ms++) {
                    mma_bf16(acc[ms][np * 2 + 0], ah[ms], bl + 0);
                    mma_bf16(acc[ms][np * 2 + 1], ah[ms], bl + 2);
                }
            }
        }
    };

    const int gid = lane >> 2;
    const int tig = lane & 3;

    // ======================= four N-passes (128 cols each) ==================
    #pragma unroll 1
    for (int pass = 0; pass < NPASS; pass++) {
        #pragma unroll
        for (int ms = 0; ms < 2; ms++)
            #pragma unroll
            for (int f = 0; f < 4; f++)
                #pragma unroll
                for (int c = 0; c < 4; c++) acc[ms][f][c] = 0.f;

        loadAB(pass, 0, 0);

        #pragma unroll 1
        for (int i = 0; i < NCH; i++) {
            const int s = i & 1;
            const bool pf = (i + 1 < NCH);
            if (pf) { loadAB(pass, i + 1, s ^ 1); CP_WAIT1(); }
            else    { CP_WAIT0(); }
            __syncthreads();
            compute(s);
            __syncthreads();
        }

        // epilogue: x = acc + hW, rowsum += v * tanh(x)
        #pragma unroll
        for (int ms = 0; ms < 2; ms++) {
            #pragma unroll
            for (int ch = 0; ch < 2; ch++) {
                const int r = wm * 32 + ms * 16 + ch * 8 + gid;
                const float* hwrow = (r >= thr) ? hw1 : hw0;
                float rs = 0.f;
                #pragma unroll
                for (int f = 0; f < 4; f++) {
                    const int n = pass * 128 + wn * 32 + f * 8 + tig * 2;
                    float x0 = acc[ms][f][ch * 2 + 0] + hwrow[n];
                    float x1 = acc[ms][f][ch * 2 + 1] + hwrow[n + 1];
                    rs += svp[n] * tanhf(x0) + svp[n + 1] * tanhf(x1);
                }
                rs += __shfl_xor_sync(0xffffffffu, rs, 1);
                rs += __shfl_xor_sync(0xffffffffu, rs, 2);
                if (tig == 0) atomicAdd(&rsm[r], rs);
            }
        }
    }

    __syncthreads();
    if (tid < TMM) g_logits[m0 + tid] = rsm[tid];
}

// ---------------------------------------------------------------------------
// softmax over S per batch. grid(64), block(256)
// ---------------------------------------------------------------------------
__global__ void softmax_kernel(float* __restrict__ out) {
    __shared__ float red[256];
    const int b = blockIdx.x;
    const int t = threadIdx.x;
    const float* row = g_logits + b * S_;
    float* orow = out + b * S_;

    float mx = -INFINITY;
    for (int i = t; i < S_; i += 256) mx = fmaxf(mx, row[i]);
    red[t] = mx;
    __syncthreads();
    for (int off = 128; off > 0; off >>= 1) {
        if (t < off) red[t] = fmaxf(red[t], red[t + off]);
        __syncthreads();
    }
    mx = red[0];
    __syncthreads();

    float sum = 0.f;
    for (int i = t; i < S_; i += 256) {
        float e = expf(row[i] - mx);
        orow[i] = e;
        sum += e;
    }
    red[t] = sum;
    __syncthreads();
    for (int off = 128; off > 0; off >>= 1) {
        if (t < off) red[t] += red[t + off];
        __syncthreads();
    }
    const float inv = 1.f / red[0];
    __syncthreads();
    for (int i = t; i < S_; i += 256) orow[i] *= inv;
}

// ---------------------------------------------------------------------------
extern "C" void kernel_launch(void* const* d_in, const int* in_sizes, int n_in,
                              void* d_out, int out_size) {
    const float* hidden = (const float*)d_in[0];   // [64, 512]
    const float* enc    = (const float*)d_in[1];   // [64, 1000, 1024]
    const float* attn_w = (const float*)d_in[2];   // [1536, 512]
    const float* attn_b = (const float*)d_in[3];   // [512]
    const float* v      = (const float*)d_in[4];   // [512]
    float* out = (float*)d_out;                    // [64, 1000]

    cudaFuncSetAttribute(gemm_kernel,
                         cudaFuncAttributeMaxDynamicSharedMemorySize, SM_TOTAL);

    conv_w_kernel<<<dim3(NCH, 4), D_>>>(attn_w);
    hw_kernel<<<dim3(B_, 4), 512>>>(hidden, attn_w, attn_b);
    conv_enc_kernel<<<M_ / 4, 256>>>(enc);
    gemm_kernel<<<M_ / TMM, NT, SM_TOTAL>>>(v);
    softmax_kernel<<<B_, 256>>>(out);
}